// round 8
// baseline (speedup 1.0000x reference)
#include <cuda_runtime.h>

// DyDepthwiseConvAtten fused: dynamic 3-tap depthwise conv along C + LayerNorm.
// B*N = 102400 rows, C = 256. R7: ILP-2 body (two rows per warp iteration,
// 8 front-batched LDG.128, interleaved shuffle chains) with PLAIN write-back
// loads AND stores — __stcs stores cost ~9us/replay in the timed graph loop
// by forcing full DRAM writeback of the output every replay.

#define C_DIM  256
#define LN_EPS 1e-5f
#define FULL   0xFFFFFFFFu

__global__ __launch_bounds__(256, 4)
void dydwconv_ln_kernel(const float* __restrict__ q,
                        const float* __restrict__ v,
                        const float* __restrict__ Ww,     // [3,256]
                        const float* __restrict__ bw,     // [3]
                        const float* __restrict__ gamma,  // [256]
                        const float* __restrict__ beta,   // [256]
                        float* __restrict__ out,
                        int rows, int total_warps)
{
    // sW[k][i][lane] = const_k[channel = lane*8 + i]; addr = i*32+lane -> conflict-free
    __shared__ float sW[5][8][32];

    const int tid  = threadIdx.x;
    const int lane = tid & 31;
    {
        const int i  = tid >> 5;
        const int ch = lane * 8 + i;
        sW[0][i][lane] = Ww[ch];
        sW[1][i][lane] = Ww[C_DIM + ch];
        sW[2][i][lane] = Ww[2 * C_DIM + ch];
        sW[3][i][lane] = gamma[ch];
        sW[4][i][lane] = beta[ch];
    }
    __syncthreads();

    const float bw0 = bw[0], bw1 = bw[1], bw2 = bw[2];

    const int warp_g = (blockIdx.x * blockDim.x + tid) >> 5;
    const int cbase  = lane * 8;
    const int rstep  = 2 * total_warps;

    for (int r0 = 2 * warp_g; r0 < rows; r0 += rstep) {
        const size_t base0 = (size_t)r0 * C_DIM + cbase;
        const size_t base1 = base0 + C_DIM;          // row r0+1 (rows is even)

        // ---- 8 front-batched 128-bit write-back loads ----
        const float4 q0a = ((const float4*)(q + base0))[0];
        const float4 q0b = ((const float4*)(q + base0))[1];
        const float4 q1a = ((const float4*)(q + base1))[0];
        const float4 q1b = ((const float4*)(q + base1))[1];
        const float4 v0a = ((const float4*)(v + base0))[0];
        const float4 v0b = ((const float4*)(v + base0))[1];
        const float4 v1a = ((const float4*)(v + base1))[0];
        const float4 v1b = ((const float4*)(v + base1))[1];

        float Q0[8] = {q0a.x,q0a.y,q0a.z,q0a.w,q0b.x,q0b.y,q0b.z,q0b.w};
        float Q1[8] = {q1a.x,q1a.y,q1a.z,q1a.w,q1b.x,q1b.y,q1b.z,q1b.w};
        float V0[8] = {v0a.x,v0a.y,v0a.z,v0a.w,v0b.x,v0b.y,v0b.z,v0b.w};
        float V1[8] = {v1a.x,v1a.y,v1a.z,v1a.w,v1b.x,v1b.y,v1b.z,v1b.w};

        // ---- dynamic weights, both rows, 6 interleaved chains ----
        float a0 = 0.f, a1 = 0.f, a2 = 0.f;   // row 0
        float b0 = 0.f, b1 = 0.f, b2 = 0.f;   // row 1
        #pragma unroll
        for (int i = 0; i < 8; i++) {
            const float w0c = sW[0][i][lane];
            const float w1c = sW[1][i][lane];
            const float w2c = sW[2][i][lane];
            a0 = fmaf(Q0[i], w0c, a0);  b0 = fmaf(Q1[i], w0c, b0);
            a1 = fmaf(Q0[i], w1c, a1);  b1 = fmaf(Q1[i], w1c, b1);
            a2 = fmaf(Q0[i], w2c, a2);  b2 = fmaf(Q1[i], w2c, b2);
        }
        #pragma unroll
        for (int off = 16; off > 0; off >>= 1) {
            a0 += __shfl_xor_sync(FULL, a0, off);
            b0 += __shfl_xor_sync(FULL, b0, off);
            a1 += __shfl_xor_sync(FULL, a1, off);
            b1 += __shfl_xor_sync(FULL, b1, off);
            a2 += __shfl_xor_sync(FULL, a2, off);
            b2 += __shfl_xor_sync(FULL, b2, off);
        }
        const float w00 = bw0 + a0, w01 = bw1 + a1, w02 = bw2 + a2;
        const float w10 = bw0 + b0, w11 = bw1 + b1, w12 = bw2 + b2;

        // ---- halo exchange (zero padded) ----
        float vl0 = __shfl_up_sync(FULL, V0[7], 1);
        float vl1 = __shfl_up_sync(FULL, V1[7], 1);
        float vr0 = __shfl_down_sync(FULL, V0[0], 1);
        float vr1 = __shfl_down_sync(FULL, V1[0], 1);
        if (lane == 0)  { vl0 = 0.f; vl1 = 0.f; }
        if (lane == 31) { vr0 = 0.f; vr1 = 0.f; }

        // ---- 3-tap conv, in place (carry register), + LN partials ----
        float s0 = 0.f, ss0 = 0.f, s1 = 0.f, ss1 = 0.f;
        float c0 = vl0, c1 = vl1;                 // V[i-1]
        #pragma unroll
        for (int i = 0; i < 8; i++) {
            const float cur0 = V0[i], cur1 = V1[i];
            const float nx0 = (i < 7) ? V0[i + 1] : vr0;
            const float nx1 = (i < 7) ? V1[i + 1] : vr1;
            const float o0 = c0 * w00 + cur0 * w01 + nx0 * w02;
            const float o1 = c1 * w10 + cur1 * w11 + nx1 * w12;
            V0[i] = o0;  V1[i] = o1;
            s0 += o0;  ss0 = fmaf(o0, o0, ss0);
            s1 += o1;  ss1 = fmaf(o1, o1, ss1);
            c0 = cur0; c1 = cur1;
        }
        #pragma unroll
        for (int off = 16; off > 0; off >>= 1) {
            s0  += __shfl_xor_sync(FULL, s0,  off);
            s1  += __shfl_xor_sync(FULL, s1,  off);
            ss0 += __shfl_xor_sync(FULL, ss0, off);
            ss1 += __shfl_xor_sync(FULL, ss1, off);
        }
        const float m0   = s0  * (1.0f / C_DIM);
        const float m1   = s1  * (1.0f / C_DIM);
        const float inv0 = rsqrtf(ss0 * (1.0f / C_DIM) - m0 * m0 + LN_EPS);
        const float inv1 = rsqrtf(ss1 * (1.0f / C_DIM) - m1 * m1 + LN_EPS);

        // ---- normalize + affine + plain write-back stores ----
        float4 r0a, r0b, r1a, r1b;
        {
            float* p0 = &r0a.x; float* p1 = &r1a.x;
            #pragma unroll
            for (int i = 0; i < 4; i++) {
                const float g = sW[3][i][lane], bt = sW[4][i][lane];
                p0[i] = (V0[i] - m0) * inv0 * g + bt;
                p1[i] = (V1[i] - m1) * inv1 * g + bt;
            }
            float* p2 = &r0b.x; float* p3 = &r1b.x;
            #pragma unroll
            for (int i = 0; i < 4; i++) {
                const float g = sW[3][i + 4][lane], bt = sW[4][i + 4][lane];
                p2[i] = (V0[i + 4] - m0) * inv0 * g + bt;
                p3[i] = (V1[i + 4] - m1) * inv1 * g + bt;
            }
        }
        ((float4*)(out + base0))[0] = r0a;
        ((float4*)(out + base0))[1] = r0b;
        ((float4*)(out + base1))[0] = r1a;
        ((float4*)(out + base1))[1] = r1b;
    }
}

extern "C" void kernel_launch(void* const* d_in, const int* in_sizes, int n_in,
                              void* d_out, int out_size)
{
    const float* q     = (const float*)d_in[0];
    const float* v     = (const float*)d_in[1];
    const float* Ww    = (const float*)d_in[2];
    const float* bw    = (const float*)d_in[3];
    const float* gamma = (const float*)d_in[4];
    const float* beta  = (const float*)d_in[5];
    float* out = (float*)d_out;

    const int rows = in_sizes[0] / C_DIM;        // 102400
    const int grid = 640;                        // 5120 warps * 10 pairs = 102400 rows
    const int total_warps = grid * (256 / 32);   // 5120
    dydwconv_ln_kernel<<<grid, 256>>>(q, v, Ww, bw, gamma, beta, out,
                                      rows, total_warps);
}

// round 9
// speedup vs baseline: 1.1351x; 1.1351x over previous
#include <cuda_runtime.h>

// DyDepthwiseConvAtten fused: dynamic 3-tap depthwise conv along C + LayerNorm.
// B*N = 102400 rows, C = 256. R8 = R3 structure (warp-per-row, 8 ch/lane,
// Ww in REGISTERS for the hot FMA chain) with two surgical changes:
//  - gamma/beta moved to conflict-free SMEM (epilogue-only LDS) to cut
//    ~16 registers -> 4 CTAs/SM instead of 3 (occupancy 32% -> ~47%)
//  - grid 1280: 10240 warps x exactly 10 rows each (perfect balance)
// Halo shuffles are interleaved with the weight-reduction shuffle tree
// (independent chains) to overlap SHFL latency.

#define C_DIM  256
#define LN_EPS 1e-5f
#define FULL   0xFFFFFFFFu

__global__ __launch_bounds__(256, 4)
void dydwconv_ln_kernel(const float* __restrict__ q,
                        const float* __restrict__ v,
                        const float* __restrict__ Ww,     // [3,256]
                        const float* __restrict__ bw,     // [3]
                        const float* __restrict__ gamma,  // [256]
                        const float* __restrict__ beta,   // [256]
                        float* __restrict__ out,
                        int rows, int total_warps)
{
    // sGB[k][i][lane] = const_k[channel = lane*8 + i]; addr = i*32+lane -> conflict-free
    __shared__ float sGB[2][8][32];

    const int tid  = threadIdx.x;
    const int lane = tid & 31;
    {
        const int i  = tid >> 5;
        const int ch = lane * 8 + i;
        sGB[0][i][lane] = gamma[ch];
        sGB[1][i][lane] = beta[ch];
    }

    const int cbase = lane * 8;

    // ---- conv weights: registers (hot FMA chain) ----
    float W0[8], W1[8], W2[8];
    {
        const float4* p;
        float4 a, b;
        p = (const float4*)(Ww + 0 * C_DIM + cbase); a = p[0]; b = p[1];
        W0[0]=a.x; W0[1]=a.y; W0[2]=a.z; W0[3]=a.w; W0[4]=b.x; W0[5]=b.y; W0[6]=b.z; W0[7]=b.w;
        p = (const float4*)(Ww + 1 * C_DIM + cbase); a = p[0]; b = p[1];
        W1[0]=a.x; W1[1]=a.y; W1[2]=a.z; W1[3]=a.w; W1[4]=b.x; W1[5]=b.y; W1[6]=b.z; W1[7]=b.w;
        p = (const float4*)(Ww + 2 * C_DIM + cbase); a = p[0]; b = p[1];
        W2[0]=a.x; W2[1]=a.y; W2[2]=a.z; W2[3]=a.w; W2[4]=b.x; W2[5]=b.y; W2[6]=b.z; W2[7]=b.w;
    }
    const float bw0 = bw[0], bw1 = bw[1], bw2 = bw[2];
    __syncthreads();

    const int warp_g = (blockIdx.x * blockDim.x + tid) >> 5;

    for (int row = warp_g; row < rows; row += total_warps) {
        const size_t base = (size_t)row * C_DIM + cbase;

        const float4 qa = ((const float4*)(q + base))[0];
        const float4 qb = ((const float4*)(q + base))[1];
        const float4 va = ((const float4*)(v + base))[0];
        const float4 vb = ((const float4*)(v + base))[1];

        float Q[8] = {qa.x, qa.y, qa.z, qa.w, qb.x, qb.y, qb.z, qb.w};
        float V[8] = {va.x, va.y, va.z, va.w, vb.x, vb.y, vb.z, vb.w};

        // ---- dynamic kernel weights: w_k = bw[k] + sum_c q[c]*Ww[k][c] ----
        float p0 = 0.f, p1 = 0.f, p2 = 0.f;
        #pragma unroll
        for (int i = 0; i < 8; i++) {
            p0 = fmaf(Q[i], W0[i], p0);
            p1 = fmaf(Q[i], W1[i], p1);
            p2 = fmaf(Q[i], W2[i], p2);
        }

        // halo shuffles are independent of the weight reduction -> issue
        // them interleaved with the first reduction stages
        float vl = __shfl_up_sync(FULL, V[7], 1);    // channel cbase-1
        float vr = __shfl_down_sync(FULL, V[0], 1);  // channel cbase+8

        #pragma unroll
        for (int off = 16; off > 0; off >>= 1) {
            p0 += __shfl_xor_sync(FULL, p0, off);
            p1 += __shfl_xor_sync(FULL, p1, off);
            p2 += __shfl_xor_sync(FULL, p2, off);
        }
        const float w0 = bw0 + p0;
        const float w1 = bw1 + p1;
        const float w2 = bw2 + p2;

        if (lane == 0)  vl = 0.f;
        if (lane == 31) vr = 0.f;

        // ---- 3-tap conv, in place (carry register), + LN partials ----
        float s = 0.f, ss = 0.f;
        float carry = vl;                     // V[i-1]
        #pragma unroll
        for (int i = 0; i < 8; i++) {
            const float cur = V[i];
            const float nxt = (i < 7) ? V[i + 1] : vr;
            const float o = carry * w0 + cur * w1 + nxt * w2;
            V[i] = o;
            s += o;
            ss = fmaf(o, o, ss);
            carry = cur;
        }
        #pragma unroll
        for (int off = 16; off > 0; off >>= 1) {
            s  += __shfl_xor_sync(FULL, s,  off);
            ss += __shfl_xor_sync(FULL, ss, off);
        }
        const float mean = s  * (1.0f / C_DIM);
        const float var  = ss * (1.0f / C_DIM) - mean * mean;
        const float inv  = rsqrtf(var + LN_EPS);

        // ---- normalize + affine (gamma/beta from SMEM, epilogue only) ----
        float4 oa, ob;
        oa.x = (V[0] - mean) * inv * sGB[0][0][lane] + sGB[1][0][lane];
        oa.y = (V[1] - mean) * inv * sGB[0][1][lane] + sGB[1][1][lane];
        oa.z = (V[2] - mean) * inv * sGB[0][2][lane] + sGB[1][2][lane];
        oa.w = (V[3] - mean) * inv * sGB[0][3][lane] + sGB[1][3][lane];
        ob.x = (V[4] - mean) * inv * sGB[0][4][lane] + sGB[1][4][lane];
        ob.y = (V[5] - mean) * inv * sGB[0][5][lane] + sGB[1][5][lane];
        ob.z = (V[6] - mean) * inv * sGB[0][6][lane] + sGB[1][6][lane];
        ob.w = (V[7] - mean) * inv * sGB[0][7][lane] + sGB[1][7][lane];
        ((float4*)(out + base))[0] = oa;
        ((float4*)(out + base))[1] = ob;
    }
}

extern "C" void kernel_launch(void* const* d_in, const int* in_sizes, int n_in,
                              void* d_out, int out_size)
{
    const float* q     = (const float*)d_in[0];
    const float* v     = (const float*)d_in[1];
    const float* Ww    = (const float*)d_in[2];
    const float* bw    = (const float*)d_in[3];
    const float* gamma = (const float*)d_in[4];
    const float* beta  = (const float*)d_in[5];
    float* out = (float*)d_out;

    const int rows = in_sizes[0] / C_DIM;        // 102400
    const int grid = 1280;                       // 10240 warps * 10 rows each
    const int total_warps = grid * (256 / 32);   // 10240
    dydwconv_ln_kernel<<<grid, 256>>>(q, v, Ww, bw, gamma, beta, out,
                                      rows, total_warps);
}